// round 11
// baseline (speedup 1.0000x reference)
#include <cuda_runtime.h>
#include <math.h>

// Fast tanh via MUFU.EX2 + fast divide. |rel err| ~1e-6. (validated R8/R9)
__device__ __forceinline__ float fast_tanh(float a) {
    float e = __expf(-2.0f * fabsf(a));
    float t = __fdividef(1.0f - e, 1.0f + e);
    return copysignf(t, a);
}

__global__ void __launch_bounds__(128, 1) matchnet_kernel(
    const float* __restrict__ X,
    const float* __restrict__ W1, const float* __restrict__ b1,
    const float* __restrict__ W2, const float* __restrict__ b2,
    const float* __restrict__ W3, const float* __restrict__ b3,
    const float* __restrict__ W4, const float* __restrict__ b4,
    float* __restrict__ out, int B)
{
    __shared__ __align__(16) float sW1[120];
    __shared__ __align__(16) float sW2[400];
    __shared__ __align__(16) float sW3[400];
    __shared__ __align__(16) float sW4[160];
    __shared__ float sb1[20], sb2s[20], sb3[20], sb4[8];

    const int t = threadIdx.x;
    for (int i = t; i < 120; i += 128) sW1[i] = W1[i];
    for (int i = t; i < 400; i += 128) sW2[i] = W2[i];
    for (int i = t; i < 400; i += 128) sW3[i] = W3[i];
    for (int i = t; i < 160; i += 128) sW4[i] = W4[i];
    if (t < 20) { sb1[t] = b1[t]; sb2s[t] = b2[t]; sb3[t] = b3[t]; }
    if (t < 8)  { sb4[t] = b4[t]; }
    __syncthreads();

    const int idx = blockIdx.x * 128 + t;
    if (idx >= B) return;

    // ---- load bids Z ----
    float Z[6];
    {
        const float2* Xp = reinterpret_cast<const float2*>(X + (size_t)idx * 6);
        float2 a0 = Xp[0], a1 = Xp[1], a2 = Xp[2];
        Z[0] = a0.x; Z[1] = a0.y; Z[2] = a1.x; Z[3] = a1.y; Z[4] = a2.x; Z[5] = a2.y;
    }

    // ---- MLP 6->20->20->20->8 (fast tanh) ----
    float h1[20], h2[20];
#pragma unroll
    for (int o = 0; o < 20; ++o) {
        const float2* w = reinterpret_cast<const float2*>(&sW1[o * 6]);
        float2 w0 = w[0], w1 = w[1], w2 = w[2];
        float a = sb1[o];
        a = fmaf(w0.x, Z[0], a); a = fmaf(w0.y, Z[1], a);
        a = fmaf(w1.x, Z[2], a); a = fmaf(w1.y, Z[3], a);
        a = fmaf(w2.x, Z[4], a); a = fmaf(w2.y, Z[5], a);
        h1[o] = fast_tanh(a);
    }
#pragma unroll
    for (int o = 0; o < 20; ++o) {
        const float4* w = reinterpret_cast<const float4*>(&sW2[o * 20]);
        float a = sb2s[o];
#pragma unroll
        for (int qq = 0; qq < 5; ++qq) {
            float4 wq = w[qq];
            a = fmaf(wq.x, h1[qq * 4 + 0], a);
            a = fmaf(wq.y, h1[qq * 4 + 1], a);
            a = fmaf(wq.z, h1[qq * 4 + 2], a);
            a = fmaf(wq.w, h1[qq * 4 + 3], a);
        }
        h2[o] = fast_tanh(a);
    }
#pragma unroll
    for (int o = 0; o < 20; ++o) {
        const float4* w = reinterpret_cast<const float4*>(&sW3[o * 20]);
        float a = sb3[o];
#pragma unroll
        for (int qq = 0; qq < 5; ++qq) {
            float4 wq = w[qq];
            a = fmaf(wq.x, h2[qq * 4 + 0], a);
            a = fmaf(wq.y, h2[qq * 4 + 1], a);
            a = fmaf(wq.z, h2[qq * 4 + 2], a);
            a = fmaf(wq.w, h2[qq * 4 + 3], a);
        }
        h1[o] = fast_tanh(a);
    }
    float z[8];
#pragma unroll
    for (int o = 0; o < 8; ++o) {
        const float4* w = reinterpret_cast<const float4*>(&sW4[o * 20]);
        float a = sb4[o];
#pragma unroll
        for (int qq = 0; qq < 5; ++qq) {
            float4 wq = w[qq];
            a = fmaf(wq.x, h1[qq * 4 + 0], a);
            a = fmaf(wq.y, h1[qq * 4 + 1], a);
            a = fmaf(wq.z, h1[qq * 4 + 2], a);
            a = fmaf(wq.w, h1[qq * 4 + 3], a);
        }
        z[o] = fast_tanh(a);
    }

    // ---- PDHG QP: scalar, all tau-multiplies as FFMA-imm (rt=1).
    // Shadow precompute (xcz, M) keeps the loop-carried dependency cycle short.
    const float TAU = 0.9f / sqrtf(26.0f);   // compile-time constant -> imm

    float x0 = fmaxf(z[0], 0.f), x1 = fmaxf(z[1], 0.f);
    float x2 = fmaxf(z[2], 0.f), x3 = fmaxf(z[3], 0.f);
    float x4 = fmaxf(z[4], 0.f), x5 = fmaxf(z[5], 0.f);
    float x6 = fmaxf(z[6], 0.f), x7 = fmaxf(z[7], 0.f);

    const float cz0 = TAU - z[0], cz1 = TAU - z[1], cz2 = TAU - z[2], cz3 = TAU - z[3];
    const float cz4 = TAU - z[4], cz5 = TAU - z[5], cz6 = TAU - z[6], cz7 = TAU - z[7];

    const float sbb0 = TAU * Z[0], sbb1 = TAU * Z[1], sbb2 = TAU * Z[2];
    const float sbb3 = TAU * Z[3], sbb4 = TAU * Z[4], sbb5 = TAU * Z[5];

    float l10 = 0.f, l11 = 0.f, l12 = 0.f, l13 = 0.f, l14 = 0.f, l15 = 0.f;
    float l20 = 0.f, l21 = 0.f, l22 = 0.f, l23 = 0.f, l24 = 0.f, l25 = 0.f, l26 = 0.f, l27 = 0.f;

    // shadow: xcz = x + cz, M = l1 - sbb
    float xc0 = x0 + cz0, xc1 = x1 + cz1, xc2 = x2 + cz2, xc3 = x3 + cz3;
    float xc4 = x4 + cz4, xc5 = x5 + cz5, xc6 = x6 + cz6, xc7 = x7 + cz7;
    float M0 = -sbb0, M1 = -sbb1, M2 = -sbb2, M3 = -sbb3, M4 = -sbb4, M5 = -sbb5;

#pragma unroll 1
    for (int it = 0; it < 150; ++it) {
        // t_j = xcz_j + TAU*l2_j  (fma-imm)
        float t0 = fmaf(TAU, l20, xc0), t1 = fmaf(TAU, l21, xc1);
        float t2 = fmaf(TAU, l22, xc2), t3 = fmaf(TAU, l23, xc3);
        float t4 = fmaf(TAU, l24, xc4), t5 = fmaf(TAU, l25, xc5);
        float t6 = fmaf(TAU, l26, xc6), t7 = fmaf(TAU, l27, xc7);

        // v_j = t_j - TAU*(S^T l1)_j, fma-imm chains
        // cols: 0:{0,3} 1:{1,4} 2:{2,5} 3:{0,1,5} 4:{2,3,5} 5:{0,3} 6:{1,4} 7:{2,4}
        float v0 = fmaf(-TAU, l10, fmaf(-TAU, l13, t0));
        float v1 = fmaf(-TAU, l11, fmaf(-TAU, l14, t1));
        float v2 = fmaf(-TAU, l12, fmaf(-TAU, l15, t2));
        float v3 = fmaf(-TAU, l10, fmaf(-TAU, l11, fmaf(-TAU, l15, t3)));
        float v4 = fmaf(-TAU, l12, fmaf(-TAU, l13, fmaf(-TAU, l15, t4)));
        float v5 = fmaf(-TAU, l10, fmaf(-TAU, l13, t5));
        float v6 = fmaf(-TAU, l11, fmaf(-TAU, l14, t6));
        float v7 = fmaf(-TAU, l12, fmaf(-TAU, l14, t7));

        // ||v||^2 tree, deepest vs (v3, v4) enter last
        float ma = v0 * v0;
        float mb = v5 * v5;
        float a0 = fmaf(v1, v1, ma);
        float a1 = fmaf(v6, v6, mb);
        float b0 = fmaf(v2, v2, a0);
        float b1 = fmaf(v7, v7, a1);
        float d0 = fmaf(v3, v3, b0);
        float d1 = fmaf(v4, v4, b1);
        float ss = d0 + d1;

        // scale = max(1 - TAU/||v||, 0); rsqrt(0)=inf clamps to 0 (ref guard)
        float r = rsqrtf(ss);
        float scale = fmaxf(fmaf(-TAU, r, 1.0f), 0.0f);

        // xn = z + scale*v ; xb = 2*xn - x  (2.0 imm, neg addend modifier)
        float xn0 = fmaf(scale, v0, z[0]); float xb0 = fmaf(2.0f, xn0, -x0);
        float xn1 = fmaf(scale, v1, z[1]); float xb1 = fmaf(2.0f, xn1, -x1);
        float xn2 = fmaf(scale, v2, z[2]); float xb2 = fmaf(2.0f, xn2, -x2);
        float xn3 = fmaf(scale, v3, z[3]); float xb3 = fmaf(2.0f, xn3, -x3);
        float xn4 = fmaf(scale, v4, z[4]); float xb4 = fmaf(2.0f, xn4, -x4);
        float xn5 = fmaf(scale, v5, z[5]); float xb5 = fmaf(2.0f, xn5, -x5);
        float xn6 = fmaf(scale, v6, z[6]); float xb6 = fmaf(2.0f, xn6, -x6);
        float xn7 = fmaf(scale, v7, z[7]); float xb7 = fmaf(2.0f, xn7, -x7);
        x0 = xn0; x1 = xn1; x2 = xn2; x3 = xn3;
        x4 = xn4; x5 = xn5; x6 = xn6; x7 = xn7;

        // shadow: next iteration's xcz (off the carried m-cycle)
        xc0 = xn0 + cz0; xc1 = xn1 + cz1; xc2 = xn2 + cz2; xc3 = xn3 + cz3;
        xc4 = xn4 + cz4; xc5 = xn5 + cz5; xc6 = xn6 + cz6; xc7 = xn7 + cz7;

        // l1_i = max(M_i + TAU*(S xb)_i, 0), fma-imm chains
        // rows: 0:{0,3,5} 1:{1,3,6} 2:{2,4,7} 3:{0,4,5} 4:{1,6,7} 5:{2,3,4}
        float u0 = fmaf(TAU, xb0, fmaf(TAU, xb3, fmaf(TAU, xb5, M0)));
        float u1 = fmaf(TAU, xb1, fmaf(TAU, xb3, fmaf(TAU, xb6, M1)));
        float u2 = fmaf(TAU, xb2, fmaf(TAU, xb4, fmaf(TAU, xb7, M2)));
        float u3 = fmaf(TAU, xb0, fmaf(TAU, xb4, fmaf(TAU, xb5, M3)));
        float u4 = fmaf(TAU, xb1, fmaf(TAU, xb6, fmaf(TAU, xb7, M4)));
        float u5 = fmaf(TAU, xb2, fmaf(TAU, xb3, fmaf(TAU, xb4, M5)));
        l10 = fmaxf(u0, 0.0f); l11 = fmaxf(u1, 0.0f); l12 = fmaxf(u2, 0.0f);
        l13 = fmaxf(u3, 0.0f); l14 = fmaxf(u4, 0.0f); l15 = fmaxf(u5, 0.0f);

        // shadow: next iteration's M
        M0 = l10 - sbb0; M1 = l11 - sbb1; M2 = l12 - sbb2;
        M3 = l13 - sbb3; M4 = l14 - sbb4; M5 = l15 - sbb5;

        // l2_j = max(l2_j - TAU*xb_j, 0)  (fma-imm + FMNMX)
        l20 = fmaxf(fmaf(-TAU, xb0, l20), 0.0f);
        l21 = fmaxf(fmaf(-TAU, xb1, l21), 0.0f);
        l22 = fmaxf(fmaf(-TAU, xb2, l22), 0.0f);
        l23 = fmaxf(fmaf(-TAU, xb3, l23), 0.0f);
        l24 = fmaxf(fmaf(-TAU, xb4, l24), 0.0f);
        l25 = fmaxf(fmaf(-TAU, xb5, l25), 0.0f);
        l26 = fmaxf(fmaf(-TAU, xb6, l26), 0.0f);
        l27 = fmaxf(fmaf(-TAU, xb7, l27), 0.0f);
    }

    // ---- store ----
    float4* op = reinterpret_cast<float4*>(out + (size_t)idx * 8);
    op[0] = make_float4(x0, x1, x2, x3);
    op[1] = make_float4(x4, x5, x6, x7);
}

extern "C" void kernel_launch(void* const* d_in, const int* in_sizes, int n_in,
                              void* d_out, int out_size)
{
    const float* X  = (const float*)d_in[0];
    const float* W1 = (const float*)d_in[1];
    const float* b1 = (const float*)d_in[2];
    const float* W2 = (const float*)d_in[3];
    const float* b2 = (const float*)d_in[4];
    const float* W3 = (const float*)d_in[5];
    const float* b3 = (const float*)d_in[6];
    const float* W4 = (const float*)d_in[7];
    const float* b4 = (const float*)d_in[8];

    const int B = in_sizes[0] / 6;
    float* out = (float*)d_out;

    const int block = 128;
    const int grid = (B + block - 1) / block;
    matchnet_kernel<<<grid, block>>>(X, W1, b1, W2, b2, W3, b3, W4, b4, out, B);
}

// round 12
// speedup vs baseline: 1.0010x; 1.0010x over previous
#include <cuda_runtime.h>
#include <math.h>

// Fast tanh via MUFU.EX2 + fast divide. |rel err| ~1e-6. (validated R8-R11)
__device__ __forceinline__ float fast_tanh(float a) {
    float e = __expf(-2.0f * fabsf(a));
    float t = __fdividef(1.0f - e, 1.0f + e);
    return copysignf(t, a);
}

__global__ void __launch_bounds__(256, 1) matchnet_kernel(
    const float* __restrict__ X,
    const float* __restrict__ W1, const float* __restrict__ b1,
    const float* __restrict__ W2, const float* __restrict__ b2,
    const float* __restrict__ W3, const float* __restrict__ b3,
    const float* __restrict__ W4, const float* __restrict__ b4,
    float* __restrict__ out, int B)
{
    __shared__ __align__(16) float sW1[120];
    __shared__ __align__(16) float sW2[400];
    __shared__ __align__(16) float sW3[400];
    __shared__ __align__(16) float sW4[160];
    __shared__ float sb1[20], sb2s[20], sb3[20], sb4[8];

    const int t = threadIdx.x;
    for (int i = t; i < 120; i += 256) sW1[i] = W1[i];
    for (int i = t; i < 400; i += 256) sW2[i] = W2[i];
    for (int i = t; i < 400; i += 256) sW3[i] = W3[i];
    for (int i = t; i < 160; i += 256) sW4[i] = W4[i];
    if (t < 20) { sb1[t] = b1[t]; sb2s[t] = b2[t]; sb3[t] = b3[t]; }
    if (t < 8)  { sb4[t] = b4[t]; }
    __syncthreads();

    const int idx = blockIdx.x * 256 + t;
    if (idx >= B) return;

    // ---- load bids Z ----
    float Z[6];
    {
        const float2* Xp = reinterpret_cast<const float2*>(X + (size_t)idx * 6);
        float2 a0 = Xp[0], a1 = Xp[1], a2 = Xp[2];
        Z[0] = a0.x; Z[1] = a0.y; Z[2] = a1.x; Z[3] = a1.y; Z[4] = a2.x; Z[5] = a2.y;
    }

    // ---- MLP 6->20->20->20->8 (fast tanh) ----
    float h1[20], h2[20];
#pragma unroll
    for (int o = 0; o < 20; ++o) {
        const float2* w = reinterpret_cast<const float2*>(&sW1[o * 6]);
        float2 w0 = w[0], w1 = w[1], w2 = w[2];
        float a = sb1[o];
        a = fmaf(w0.x, Z[0], a); a = fmaf(w0.y, Z[1], a);
        a = fmaf(w1.x, Z[2], a); a = fmaf(w1.y, Z[3], a);
        a = fmaf(w2.x, Z[4], a); a = fmaf(w2.y, Z[5], a);
        h1[o] = fast_tanh(a);
    }
#pragma unroll
    for (int o = 0; o < 20; ++o) {
        const float4* w = reinterpret_cast<const float4*>(&sW2[o * 20]);
        float a = sb2s[o];
#pragma unroll
        for (int qq = 0; qq < 5; ++qq) {
            float4 wq = w[qq];
            a = fmaf(wq.x, h1[qq * 4 + 0], a);
            a = fmaf(wq.y, h1[qq * 4 + 1], a);
            a = fmaf(wq.z, h1[qq * 4 + 2], a);
            a = fmaf(wq.w, h1[qq * 4 + 3], a);
        }
        h2[o] = fast_tanh(a);
    }
#pragma unroll
    for (int o = 0; o < 20; ++o) {
        const float4* w = reinterpret_cast<const float4*>(&sW3[o * 20]);
        float a = sb3[o];
#pragma unroll
        for (int qq = 0; qq < 5; ++qq) {
            float4 wq = w[qq];
            a = fmaf(wq.x, h2[qq * 4 + 0], a);
            a = fmaf(wq.y, h2[qq * 4 + 1], a);
            a = fmaf(wq.z, h2[qq * 4 + 2], a);
            a = fmaf(wq.w, h2[qq * 4 + 3], a);
        }
        h1[o] = fast_tanh(a);
    }
    float z[8];
#pragma unroll
    for (int o = 0; o < 8; ++o) {
        const float4* w = reinterpret_cast<const float4*>(&sW4[o * 20]);
        float a = sb4[o];
#pragma unroll
        for (int qq = 0; qq < 5; ++qq) {
            float4 wq = w[qq];
            a = fmaf(wq.x, h1[qq * 4 + 0], a);
            a = fmaf(wq.y, h1[qq * 4 + 1], a);
            a = fmaf(wq.z, h1[qq * 4 + 2], a);
            a = fmaf(wq.w, h1[qq * 4 + 3], a);
        }
        z[o] = fast_tanh(a);
    }

    // ---- WARP PHASE SKEW ----
    // Each SMSP hosts warps w and w+4 of this block (block=256, grid=128 ->
    // one block per busy SM). Delay warps 4-7 by a ~160-cycle dependent FFMA
    // chain so co-resident warps run anti-phased: one issues while the other
    // sits in its per-iteration rsqrt bubble. Numerically inert; the guarded
    // store is never taken (sk stays O(1)) but prevents dead-code elimination.
    if (threadIdx.x & 128) {
        float sk = Z[0] + 1.5f;
#pragma unroll
        for (int i = 0; i < 40; ++i) sk = fmaf(sk, 0.9999999f, 1e-7f);
        if (sk > 1e37f) out[idx] = sk;
    }

    // ---- PDHG QP: scalar, tau-multiplies as FFMA-imm (rt=1).
    // Shadow precompute (xcz, M) keeps the loop-carried dependency cycle short.
    const float TAU = 0.9f / sqrtf(26.0f);

    float x0 = fmaxf(z[0], 0.f), x1 = fmaxf(z[1], 0.f);
    float x2 = fmaxf(z[2], 0.f), x3 = fmaxf(z[3], 0.f);
    float x4 = fmaxf(z[4], 0.f), x5 = fmaxf(z[5], 0.f);
    float x6 = fmaxf(z[6], 0.f), x7 = fmaxf(z[7], 0.f);

    const float cz0 = TAU - z[0], cz1 = TAU - z[1], cz2 = TAU - z[2], cz3 = TAU - z[3];
    const float cz4 = TAU - z[4], cz5 = TAU - z[5], cz6 = TAU - z[6], cz7 = TAU - z[7];

    const float sbb0 = TAU * Z[0], sbb1 = TAU * Z[1], sbb2 = TAU * Z[2];
    const float sbb3 = TAU * Z[3], sbb4 = TAU * Z[4], sbb5 = TAU * Z[5];

    float l10 = 0.f, l11 = 0.f, l12 = 0.f, l13 = 0.f, l14 = 0.f, l15 = 0.f;
    float l20 = 0.f, l21 = 0.f, l22 = 0.f, l23 = 0.f, l24 = 0.f, l25 = 0.f, l26 = 0.f, l27 = 0.f;

    // shadow: xcz = x + cz, M = l1 - sbb
    float xc0 = x0 + cz0, xc1 = x1 + cz1, xc2 = x2 + cz2, xc3 = x3 + cz3;
    float xc4 = x4 + cz4, xc5 = x5 + cz5, xc6 = x6 + cz6, xc7 = x7 + cz7;
    float M0 = -sbb0, M1 = -sbb1, M2 = -sbb2, M3 = -sbb3, M4 = -sbb4, M5 = -sbb5;

#pragma unroll 1
    for (int it = 0; it < 150; ++it) {
        // t_j = xcz_j + TAU*l2_j  (fma-imm)
        float t0 = fmaf(TAU, l20, xc0), t1 = fmaf(TAU, l21, xc1);
        float t2 = fmaf(TAU, l22, xc2), t3 = fmaf(TAU, l23, xc3);
        float t4 = fmaf(TAU, l24, xc4), t5 = fmaf(TAU, l25, xc5);
        float t6 = fmaf(TAU, l26, xc6), t7 = fmaf(TAU, l27, xc7);

        // v_j = t_j - TAU*(S^T l1)_j, fma-imm chains
        // cols: 0:{0,3} 1:{1,4} 2:{2,5} 3:{0,1,5} 4:{2,3,5} 5:{0,3} 6:{1,4} 7:{2,4}
        float v0 = fmaf(-TAU, l10, fmaf(-TAU, l13, t0));
        float v1 = fmaf(-TAU, l11, fmaf(-TAU, l14, t1));
        float v2 = fmaf(-TAU, l12, fmaf(-TAU, l15, t2));
        float v3 = fmaf(-TAU, l10, fmaf(-TAU, l11, fmaf(-TAU, l15, t3)));
        float v4 = fmaf(-TAU, l12, fmaf(-TAU, l13, fmaf(-TAU, l15, t4)));
        float v5 = fmaf(-TAU, l10, fmaf(-TAU, l13, t5));
        float v6 = fmaf(-TAU, l11, fmaf(-TAU, l14, t6));
        float v7 = fmaf(-TAU, l12, fmaf(-TAU, l14, t7));

        // ||v||^2 tree, deepest vs (v3, v4) enter last
        float ma = v0 * v0;
        float mb = v5 * v5;
        float a0 = fmaf(v1, v1, ma);
        float a1 = fmaf(v6, v6, mb);
        float b0 = fmaf(v2, v2, a0);
        float b1 = fmaf(v7, v7, a1);
        float d0 = fmaf(v3, v3, b0);
        float d1 = fmaf(v4, v4, b1);
        float ss = d0 + d1;

        // scale = max(1 - TAU/||v||, 0); rsqrt(0)=inf clamps to 0 (ref guard)
        float r = rsqrtf(ss);
        float scale = fmaxf(fmaf(-TAU, r, 1.0f), 0.0f);

        // xn = z + scale*v ; xb = 2*xn - x
        float xn0 = fmaf(scale, v0, z[0]); float xb0 = fmaf(2.0f, xn0, -x0);
        float xn1 = fmaf(scale, v1, z[1]); float xb1 = fmaf(2.0f, xn1, -x1);
        float xn2 = fmaf(scale, v2, z[2]); float xb2 = fmaf(2.0f, xn2, -x2);
        float xn3 = fmaf(scale, v3, z[3]); float xb3 = fmaf(2.0f, xn3, -x3);
        float xn4 = fmaf(scale, v4, z[4]); float xb4 = fmaf(2.0f, xn4, -x4);
        float xn5 = fmaf(scale, v5, z[5]); float xb5 = fmaf(2.0f, xn5, -x5);
        float xn6 = fmaf(scale, v6, z[6]); float xb6 = fmaf(2.0f, xn6, -x6);
        float xn7 = fmaf(scale, v7, z[7]); float xb7 = fmaf(2.0f, xn7, -x7);
        x0 = xn0; x1 = xn1; x2 = xn2; x3 = xn3;
        x4 = xn4; x5 = xn5; x6 = xn6; x7 = xn7;

        // shadow: next iteration's xcz (off the carried cycle)
        xc0 = xn0 + cz0; xc1 = xn1 + cz1; xc2 = xn2 + cz2; xc3 = xn3 + cz3;
        xc4 = xn4 + cz4; xc5 = xn5 + cz5; xc6 = xn6 + cz6; xc7 = xn7 + cz7;

        // l1_i = max(M_i + TAU*(S xb)_i, 0), fma-imm chains
        // rows: 0:{0,3,5} 1:{1,3,6} 2:{2,4,7} 3:{0,4,5} 4:{1,6,7} 5:{2,3,4}
        float u0 = fmaf(TAU, xb0, fmaf(TAU, xb3, fmaf(TAU, xb5, M0)));
        float u1 = fmaf(TAU, xb1, fmaf(TAU, xb3, fmaf(TAU, xb6, M1)));
        float u2 = fmaf(TAU, xb2, fmaf(TAU, xb4, fmaf(TAU, xb7, M2)));
        float u3 = fmaf(TAU, xb0, fmaf(TAU, xb4, fmaf(TAU, xb5, M3)));
        float u4 = fmaf(TAU, xb1, fmaf(TAU, xb6, fmaf(TAU, xb7, M4)));
        float u5 = fmaf(TAU, xb2, fmaf(TAU, xb3, fmaf(TAU, xb4, M5)));
        l10 = fmaxf(u0, 0.0f); l11 = fmaxf(u1, 0.0f); l12 = fmaxf(u2, 0.0f);
        l13 = fmaxf(u3, 0.0f); l14 = fmaxf(u4, 0.0f); l15 = fmaxf(u5, 0.0f);

        // shadow: next iteration's M
        M0 = l10 - sbb0; M1 = l11 - sbb1; M2 = l12 - sbb2;
        M3 = l13 - sbb3; M4 = l14 - sbb4; M5 = l15 - sbb5;

        // l2_j = max(l2_j - TAU*xb_j, 0)  (fma-imm + FMNMX)
        l20 = fmaxf(fmaf(-TAU, xb0, l20), 0.0f);
        l21 = fmaxf(fmaf(-TAU, xb1, l21), 0.0f);
        l22 = fmaxf(fmaf(-TAU, xb2, l22), 0.0f);
        l23 = fmaxf(fmaf(-TAU, xb3, l23), 0.0f);
        l24 = fmaxf(fmaf(-TAU, xb4, l24), 0.0f);
        l25 = fmaxf(fmaf(-TAU, xb5, l25), 0.0f);
        l26 = fmaxf(fmaf(-TAU, xb6, l26), 0.0f);
        l27 = fmaxf(fmaf(-TAU, xb7, l27), 0.0f);
    }

    // ---- store ----
    float4* op = reinterpret_cast<float4*>(out + (size_t)idx * 8);
    op[0] = make_float4(x0, x1, x2, x3);
    op[1] = make_float4(x4, x5, x6, x7);
}

extern "C" void kernel_launch(void* const* d_in, const int* in_sizes, int n_in,
                              void* d_out, int out_size)
{
    const float* X  = (const float*)d_in[0];
    const float* W1 = (const float*)d_in[1];
    const float* b1 = (const float*)d_in[2];
    const float* W2 = (const float*)d_in[3];
    const float* b2 = (const float*)d_in[4];
    const float* W3 = (const float*)d_in[5];
    const float* b3 = (const float*)d_in[6];
    const float* W4 = (const float*)d_in[7];
    const float* b4 = (const float*)d_in[8];

    const int B = in_sizes[0] / 6;
    float* out = (float*)d_out;

    // block=256, grid=128: one block per busy SM -> SMSP s hosts warps s and
    // s+4, which carry opposite skew parities (threadIdx.x & 128).
    const int block = 256;
    const int grid = (B + block - 1) / block;
    matchnet_kernel<<<grid, block>>>(X, W1, b1, W2, b2, W3, b3, W4, b4, out, B);
}